// round 14
// baseline (speedup 1.0000x reference)
#include <cuda_runtime.h>
#include <cuda_fp16.h>
#include <math.h>
#include <stdint.h>

#define DH 128
#define NMAX 50016
#define EMAX 800000

// ---------------- scratch (device globals; no allocation allowed) ----------------
__device__ float  g_dinv[NMAX];
__device__ int    g_deg[NMAX];
__device__ int    g_rowptr[NMAX + 1];
__device__ int    g_cursor[NMAX];
__device__ int    g_adj[EMAX];
__device__ __half g_h1h[(size_t)NMAX * DH];  // fp16 dinv-scaled transformed features (gather operand)
__device__ float  g_h2[(size_t)NMAX * DH];   // aggregated features (fp32)
__device__ float  g_sum0[DH];
__device__ float  g_sq0[DH];
__device__ float  g_sum1[DH];
__device__ float  g_sq1[DH];

// ---------------- helpers ----------------
__device__ __forceinline__ uint32_t f2tf32(float x) {
    uint32_t u;
    asm("cvt.rna.tf32.f32 %0, %1;" : "=r"(u) : "f"(x));
    return u;
}

__device__ __forceinline__ void mma_tf32(float* c, const uint32_t* a, uint32_t b0, uint32_t b1) {
    asm volatile(
        "mma.sync.aligned.m16n8k8.row.col.f32.tf32.tf32.f32 "
        "{%0,%1,%2,%3}, {%4,%5,%6,%7}, {%8,%9}, {%0,%1,%2,%3};"
        : "+f"(c[0]), "+f"(c[1]), "+f"(c[2]), "+f"(c[3])
        : "r"(a[0]), "r"(a[1]), "r"(a[2]), "r"(a[3]), "r"(b0), "r"(b1));
}

__device__ __forceinline__ void acc_row128(float* a, const uint4& v) {
    float2 f0 = __half22float2(*reinterpret_cast<const __half2*>(&v.x));
    float2 f1 = __half22float2(*reinterpret_cast<const __half2*>(&v.y));
    float2 f2 = __half22float2(*reinterpret_cast<const __half2*>(&v.z));
    float2 f3 = __half22float2(*reinterpret_cast<const __half2*>(&v.w));
    a[0] += f0.x; a[1] += f0.y; a[2] += f1.x; a[3] += f1.y;
    a[4] += f2.x; a[5] += f2.y; a[6] += f3.x; a[7] += f3.y;
}

// ---------------- CSR build ----------------
__global__ void k_count(const int* __restrict__ dst, int* deg, int E) {
    int e = blockIdx.x * blockDim.x + threadIdx.x;
    if (e < E) atomicAdd(&deg[dst[e]], 1);
}

__global__ __launch_bounds__(1024) void k_scan(const int* __restrict__ deg,
                                               int* rowptr, int* cursor,
                                               float* dinv, int n)
{
    __shared__ int sm[1024];
    const int T = 1024;
    int tid = threadIdx.x;
    int chunk = (n + T - 1) / T;
    int beg = tid * chunk;
    int end = min(beg + chunk, n);
    if (beg > n) beg = n;
    if (end < beg) end = beg;

    int s = 0;
    for (int i = beg; i < end; i++) s += deg[i];
    sm[tid] = s;
    __syncthreads();
    for (int off = 1; off < T; off <<= 1) {
        int v = (tid >= off) ? sm[tid - off] : 0;
        __syncthreads();
        sm[tid] += v;
        __syncthreads();
    }
    int run = sm[tid] - s;
    for (int i = beg; i < end; i++) {
        int d = deg[i];
        rowptr[i] = run;
        cursor[i] = run;
        dinv[i] = rsqrtf((float)d + 1.0f);
        run += d;
    }
    if (tid == T - 1) rowptr[n] = sm[T - 1];
}

__global__ void k_fill(const int* __restrict__ src, const int* __restrict__ dst,
                       int* cursor, int* adj, int E)
{
    int e = blockIdx.x * blockDim.x + threadIdx.x;
    if (e < E) {
        int d = dst[e];
        int p = atomicAdd(&cursor[d], 1);
        adj[p] = src[e];
    }
}

// ---------------- tf32 tensor-core GEMM: Ch[n,128] = fp16( dinv * (op(A) @ W) ) ----------------
// BM=64 tile, 8 warps (4x2), warp = 16x64 via 8 m16n8k8 MMAs.
// BN: per-block compute of bn affine from (ssum,ssq,gamma,beta); applied to A on load.
// Block 0 zeroes (zsum,zsq) for the aggregation kernel that follows.
template <bool BN>
__global__ __launch_bounds__(256) void gemm128_tc(
    const float* __restrict__ A, const float* __restrict__ W,
    __half* __restrict__ Ch, const float* __restrict__ dinv,
    const float* __restrict__ gamma, const float* __restrict__ beta,
    const float* __restrict__ ssum, const float* __restrict__ ssq,
    float* zsum, float* zsq, float inv_n, int nrows)
{
    __shared__ uint32_t sA[64][36];
    __shared__ uint32_t sW[32][136];
    __shared__ float sbna[DH];
    __shared__ float sbnb[DH];

    int tid = threadIdx.x;
    if (BN) {
        if (tid < DH) {
            float mu = ssum[tid] * inv_n;
            float var = ssq[tid] * inv_n - mu * mu;
            float rstd = rsqrtf(var + 1e-5f);
            float aa = gamma[tid] * rstd;
            sbna[tid] = aa;
            sbnb[tid] = beta[tid] - mu * aa;
        }
        __syncthreads();
    }
    if (blockIdx.x == 0 && tid < DH) {
        zsum[tid] = 0.f;
        zsq[tid] = 0.f;
    }

    int lane = tid & 31, warp = tid >> 5;
    int gq = lane >> 2, tq = lane & 3;
    int warpM = warp >> 1, warpN = warp & 1;
    int row0 = blockIdx.x * 64;

    float acc[8][4];
#pragma unroll
    for (int nt = 0; nt < 8; nt++)
#pragma unroll
        for (int i = 0; i < 4; i++) acc[nt][i] = 0.f;

    for (int slab = 0; slab < 4; slab++) {
        int kt = slab * 32;
#pragma unroll
        for (int i = 0; i < 2; i++) {
            int f = tid + i * 256;
            int r = f >> 3;
            int c4 = (f & 7) * 4;
            int gr = row0 + r;
            float4 v = (gr < nrows) ? *(const float4*)(A + (size_t)gr * 128 + kt + c4)
                                    : make_float4(0.f, 0.f, 0.f, 0.f);
            if (BN) {
                int c = kt + c4;
                v.x = fmaxf(v.x * sbna[c + 0] + sbnb[c + 0], 0.f);
                v.y = fmaxf(v.y * sbna[c + 1] + sbnb[c + 1], 0.f);
                v.z = fmaxf(v.z * sbna[c + 2] + sbnb[c + 2], 0.f);
                v.w = fmaxf(v.w * sbna[c + 3] + sbnb[c + 3], 0.f);
            }
            uint4 u = make_uint4(f2tf32(v.x), f2tf32(v.y), f2tf32(v.z), f2tf32(v.w));
            *(uint4*)&sA[r][c4] = u;
        }
#pragma unroll
        for (int i = 0; i < 4; i++) {
            int f = tid + i * 256;
            int kr = f >> 5;
            int c4 = (f & 31) * 4;
            float4 v = *(const float4*)(W + (size_t)(kt + kr) * 128 + c4);
            uint4 u = make_uint4(f2tf32(v.x), f2tf32(v.y), f2tf32(v.z), f2tf32(v.w));
            *(uint4*)&sW[kr][c4] = u;
        }
        __syncthreads();

#pragma unroll
        for (int k8 = 0; k8 < 4; k8++) {
            int kk = k8 * 8;
            uint32_t a[4];
            {
                int r = warpM * 16 + gq;
                a[0] = sA[r][kk + tq];
                a[1] = sA[r + 8][kk + tq];
                a[2] = sA[r][kk + tq + 4];
                a[3] = sA[r + 8][kk + tq + 4];
            }
#pragma unroll
            for (int nt = 0; nt < 8; nt++) {
                int n = warpN * 64 + nt * 8 + gq;
                uint32_t b0 = sW[kk + tq][n];
                uint32_t b1 = sW[kk + tq + 4][n];
                mma_tf32(acc[nt], a, b0, b1);
            }
        }
        __syncthreads();
    }

    {
        int r0 = row0 + warpM * 16 + gq;
        int r1 = r0 + 8;
        float d0 = (r0 < nrows) ? dinv[r0] : 0.f;
        float d1 = (r1 < nrows) ? dinv[r1] : 0.f;
#pragma unroll
        for (int nt = 0; nt < 8; nt++) {
            int col = warpN * 64 + nt * 8 + 2 * tq;
            if (r0 < nrows) {
                __half2 h = __floats2half2_rn(acc[nt][0] * d0, acc[nt][1] * d0);
                *(__half2*)(Ch + (size_t)r0 * 128 + col) = h;
            }
            if (r1 < nrows) {
                __half2 h = __floats2half2_rn(acc[nt][2] * d1, acc[nt][3] * d1);
                *(__half2*)(Ch + (size_t)r1 * 128 + col) = h;
            }
        }
    }
}

// ---------------- SGEMM: Ch[n,40] = fp16( dinv * (bn_relu(A)[n,128] @ W[128,40]) ) ----------------
// BN affine computed per-block from (ssum,ssq,gamma,beta).
__global__ __launch_bounds__(256) void gemm40(
    const float* __restrict__ A, const float* __restrict__ W,
    __half* __restrict__ Ch, const float* __restrict__ dinv,
    const float* __restrict__ gamma, const float* __restrict__ beta,
    const float* __restrict__ ssum, const float* __restrict__ ssq,
    float inv_n, int nrows)
{
    __shared__ float sA[16][64];
    __shared__ float sW[16][40];
    __shared__ float sbna[DH];
    __shared__ float sbnb[DH];
    int tid = threadIdx.x;
    if (tid < DH) {
        float mu = ssum[tid] * inv_n;
        float var = ssq[tid] * inv_n - mu * mu;
        float rstd = rsqrtf(var + 1e-5f);
        float aa = gamma[tid] * rstd;
        sbna[tid] = aa;
        sbnb[tid] = beta[tid] - mu * aa;
    }
    __syncthreads();

    int tx = tid & 15, ty = tid >> 4;
    int row0 = blockIdx.x * 64;

    float acc[4][3];
#pragma unroll
    for (int i = 0; i < 4; i++)
#pragma unroll
        for (int j = 0; j < 3; j++) acc[i][j] = 0.f;

    for (int kt = 0; kt < 128; kt += 16) {
        {
            int r = tid >> 2;
            int k4 = (tid & 3) * 4;
            int gr = row0 + r;
            float4 v = (gr < nrows) ? *(const float4*)(A + (size_t)gr * 128 + kt + k4)
                                    : make_float4(0.f, 0.f, 0.f, 0.f);
            int c = kt + k4;
            v.x = fmaxf(v.x * sbna[c + 0] + sbnb[c + 0], 0.f);
            v.y = fmaxf(v.y * sbna[c + 1] + sbnb[c + 1], 0.f);
            v.z = fmaxf(v.z * sbna[c + 2] + sbnb[c + 2], 0.f);
            v.w = fmaxf(v.w * sbna[c + 3] + sbnb[c + 3], 0.f);
            sA[k4 + 0][r] = v.x; sA[k4 + 1][r] = v.y;
            sA[k4 + 2][r] = v.z; sA[k4 + 3][r] = v.w;
        }
        for (int t = tid; t < 16 * 40; t += 256) {
            int kr = t / 40, c = t % 40;
            sW[kr][c] = W[(size_t)(kt + kr) * 40 + c];
        }
        __syncthreads();

#pragma unroll
        for (int k = 0; k < 16; k++) {
            float4 av = *(float4*)&sA[k][ty * 4];
            float a[4] = {av.x, av.y, av.z, av.w};
            float w0 = sW[k][tx];
            float w1 = sW[k][tx + 16];
            float w2 = (tx < 8) ? sW[k][tx + 32] : 0.f;
#pragma unroll
            for (int i = 0; i < 4; i++) {
                acc[i][0] += a[i] * w0;
                acc[i][1] += a[i] * w1;
                acc[i][2] += a[i] * w2;
            }
        }
        __syncthreads();
    }

#pragma unroll
    for (int i = 0; i < 4; i++) {
        int gr = row0 + ty * 4 + i;
        if (gr >= nrows) continue;
        float di = dinv[gr];
        Ch[(size_t)gr * 40 + tx]      = __float2half_rn(acc[i][0] * di);
        Ch[(size_t)gr * 40 + tx + 16] = __float2half_rn(acc[i][1] * di);
        if (tx < 8) Ch[(size_t)gr * 40 + tx + 32] = __float2half_rn(acc[i][2] * di);
    }
}

// ---------------- CSR gather aggregation, D=128 ----------------
// PAIRED fp16 gathers + depth-2 index / depth-1 data software pipeline:
// iteration i issues iteration i+1's gathers (indices prefetched two iters
// back) BEFORE consuming iteration i's data.
template <bool STATS>
__global__ __launch_bounds__(256) void k_agg128(
    const __half* __restrict__ hs, const int* __restrict__ rowptr,
    const int* __restrict__ adj, const float* __restrict__ dinv,
    const float* __restrict__ bias, float* __restrict__ out,
    float* osum, float* osq, int n)
{
    int tid = threadIdx.x;
    int warp = tid >> 5, lane = tid & 31;
    int side = lane >> 4;
    int fl = lane & 15;
    int g = fl * 8;

    float b[8];
    *(float4*)&b[0] = __ldg((const float4*)(bias + g));
    *(float4*)&b[4] = __ldg((const float4*)(bias + g + 4));

    float s[8], q[8];
#pragma unroll
    for (int i = 0; i < 8; i++) { s[i] = 0.f; q[i] = 0.f; }

    for (int node = blockIdx.x * 8 + warp; node < n; node += gridDim.x * 8) {
        int beg = __ldg(rowptr + node);
        int end = __ldg(rowptr + node + 1);

        float a[8];
        if (side == 0) {
            uint4 v = __ldg((const uint4*)(hs + (size_t)node * DH + g));
#pragma unroll
            for (int i = 0; i < 8; i++) a[i] = 0.f;
            acc_row128(a, v);
        } else {
#pragma unroll
            for (int i = 0; i < 8; i++) a[i] = 0.f;
        }

        int j = beg;
        // pipelined main loop (8 neighbors/iter)
        bool haveA = (j + 8 <= end);
        bool haveB = (j + 16 <= end);
        int ixB[4];
        uint4 vA[4];
        if (haveA) {
            int ixA[4];
#pragma unroll
            for (int u = 0; u < 4; u++) ixA[u] = __ldg(adj + j + 2 * u + side);
            if (haveB) {
#pragma unroll
                for (int u = 0; u < 4; u++) ixB[u] = __ldg(adj + j + 8 + 2 * u + side);
            }
#pragma unroll
            for (int u = 0; u < 4; u++)
                vA[u] = __ldg((const uint4*)(hs + (size_t)ixA[u] * DH + g));
        }
        while (haveA) {
            bool haveC = (j + 24 <= end);
            int ixC[4];
            if (haveC) {
#pragma unroll
                for (int u = 0; u < 4; u++) ixC[u] = __ldg(adj + j + 16 + 2 * u + side);
            }
            uint4 vB[4];
            if (haveB) {
#pragma unroll
                for (int u = 0; u < 4; u++)
                    vB[u] = __ldg((const uint4*)(hs + (size_t)ixB[u] * DH + g));
            }
            // consume current
#pragma unroll
            for (int u = 0; u < 4; u++) acc_row128(a, vA[u]);
            // shift
#pragma unroll
            for (int u = 0; u < 4; u++) { vA[u] = vB[u]; ixB[u] = ixC[u]; }
            j += 8;
            haveA = haveB; haveB = haveC;
        }
        // pair tail
        for (; j + 2 <= end; j += 2) {
            int ix = __ldg(adj + j + side);
            uint4 v = __ldg((const uint4*)(hs + (size_t)ix * DH + g));
            acc_row128(a, v);
        }
        if (j < end && side == 0) {
            int ix = __ldg(adj + j);
            uint4 v = __ldg((const uint4*)(hs + (size_t)ix * DH + g));
            acc_row128(a, v);
        }

#pragma unroll
        for (int i = 0; i < 8; i++)
            a[i] += __shfl_xor_sync(0xffffffffu, a[i], 16);

        if (side == 0) {
            float di = dinv[node];
            float o[8];
#pragma unroll
            for (int i = 0; i < 8; i++) o[i] = b[i] + a[i] * di;
            *(float4*)(out + (size_t)node * DH + g) =
                make_float4(o[0], o[1], o[2], o[3]);
            *(float4*)(out + (size_t)node * DH + g + 4) =
                make_float4(o[4], o[5], o[6], o[7]);
            if (STATS) {
#pragma unroll
                for (int i = 0; i < 8; i++) { s[i] += o[i]; q[i] += o[i] * o[i]; }
            }
        }
    }

    if (STATS) {
        __shared__ float rsum[8][DH];
        __shared__ float rsq[8][DH];
        if (side == 0) {
#pragma unroll
            for (int i = 0; i < 8; i++) {
                rsum[warp][g + i] = s[i];
                rsq[warp][g + i] = q[i];
            }
        }
        __syncthreads();
        if (tid < DH) {
            float aa = 0.f, bb = 0.f;
#pragma unroll
            for (int w = 0; w < 8; w++) { aa += rsum[w][tid]; bb += rsq[w][tid]; }
            atomicAdd(&osum[tid], aa);
            atomicAdd(&osq[tid], bb);
        }
    }
}

// ---------------- CSR gather aggregation D=40 (fp16 gather, index prefetch) + log_softmax ----------------
__global__ __launch_bounds__(256) void k_agg40(
    const __half* __restrict__ hs, const int* __restrict__ rowptr,
    const int* __restrict__ adj, const float* __restrict__ dinv,
    const float* __restrict__ bias, float* __restrict__ out, int n)
{
    int tid = threadIdx.x;
    int warp = tid >> 5, lane = tid & 31;
    int node = blockIdx.x * 8 + warp;
    if (node >= n) return;

    float4 o = make_float4(0.f, 0.f, 0.f, 0.f);
    if (lane < 10) {
        int g = lane * 4;
        int beg = __ldg(rowptr + node);
        int end = __ldg(rowptr + node + 1);
        float4 acc;
        {
            uint2 rw = __ldg((const uint2*)(hs + (size_t)node * 40 + g));
            float2 f0 = __half22float2(*reinterpret_cast<__half2*>(&rw.x));
            float2 f1 = __half22float2(*reinterpret_cast<__half2*>(&rw.y));
            acc = make_float4(f0.x, f0.y, f1.x, f1.y);
        }
        int j = beg;
        int sxn[8];
        bool have = (j + 8 <= end);
        if (have) {
#pragma unroll
            for (int u = 0; u < 8; u++) sxn[u] = __ldg(adj + j + u);
        }
        while (have) {
            int sx[8];
#pragma unroll
            for (int u = 0; u < 8; u++) sx[u] = sxn[u];
            int jn = j + 8;
            bool haven = (jn + 8 <= end);
            if (haven) {
#pragma unroll
                for (int u = 0; u < 8; u++) sxn[u] = __ldg(adj + jn + u);
            }
            uint2 rw[8];
#pragma unroll
            for (int u = 0; u < 8; u++)
                rw[u] = __ldg((const uint2*)(hs + (size_t)sx[u] * 40 + g));
#pragma unroll
            for (int u = 0; u < 8; u++) {
                float2 f0 = __half22float2(*reinterpret_cast<__half2*>(&rw[u].x));
                float2 f1 = __half22float2(*reinterpret_cast<__half2*>(&rw[u].y));
                acc.x += f0.x; acc.y += f0.y; acc.z += f1.x; acc.w += f1.y;
            }
            j = jn; have = haven;
        }
        for (; j < end; j++) {
            int s = __ldg(adj + j);
            uint2 rw = __ldg((const uint2*)(hs + (size_t)s * 40 + g));
            float2 f0 = __half22float2(*reinterpret_cast<__half2*>(&rw.x));
            float2 f1 = __half22float2(*reinterpret_cast<__half2*>(&rw.y));
            acc.x += f0.x; acc.y += f0.y; acc.z += f1.x; acc.w += f1.y;
        }
        float di = dinv[node];
        float4 bvv = __ldg((const float4*)(bias + g));
        o = make_float4(bvv.x + acc.x * di, bvv.y + acc.y * di,
                        bvv.z + acc.z * di, bvv.w + acc.w * di);
    }

    float m = (lane < 10) ? fmaxf(fmaxf(o.x, o.y), fmaxf(o.z, o.w)) : -INFINITY;
#pragma unroll
    for (int off = 16; off > 0; off >>= 1)
        m = fmaxf(m, __shfl_xor_sync(0xffffffffu, m, off));
    float s = (lane < 10) ? (expf(o.x - m) + expf(o.y - m) + expf(o.z - m) + expf(o.w - m)) : 0.f;
#pragma unroll
    for (int off = 16; off > 0; off >>= 1)
        s += __shfl_xor_sync(0xffffffffu, s, off);
    float l = m + logf(s);
    if (lane < 10) {
        *(float4*)(out + (size_t)node * 40 + lane * 4) =
            make_float4(o.x - l, o.y - l, o.z - l, o.w - l);
    }
}

// ---------------- host orchestration ----------------
extern "C" void kernel_launch(void* const* d_in, const int* in_sizes, int n_in,
                              void* d_out, int out_size)
{
    const float* x   = (const float*)d_in[0];
    const int*   ei  = (const int*)d_in[1];
    const float* W0  = (const float*)d_in[2];
    const float* b0  = (const float*)d_in[3];
    const float* W1  = (const float*)d_in[4];
    const float* b1  = (const float*)d_in[5];
    const float* W2  = (const float*)d_in[6];
    const float* b2  = (const float*)d_in[7];
    const float* g0  = (const float*)d_in[8];
    const float* bt0 = (const float*)d_in[9];
    const float* g1  = (const float*)d_in[10];
    const float* bt1 = (const float*)d_in[11];
    float* out = (float*)d_out;

    int N = in_sizes[0] / DH;
    int E = in_sizes[1] / 2;
    const int* src = ei;
    const int* dst = ei + E;

    float *dinv, *h2, *sum0, *sq0, *sum1, *sq1;
    __half* h1h;
    int *deg, *rowptr, *cursor, *adj;
    cudaGetSymbolAddress((void**)&dinv, g_dinv);
    cudaGetSymbolAddress((void**)&h1h, g_h1h);
    cudaGetSymbolAddress((void**)&h2, g_h2);
    cudaGetSymbolAddress((void**)&sum0, g_sum0);
    cudaGetSymbolAddress((void**)&sq0, g_sq0);
    cudaGetSymbolAddress((void**)&sum1, g_sum1);
    cudaGetSymbolAddress((void**)&sq1, g_sq1);
    cudaGetSymbolAddress((void**)&deg, g_deg);
    cudaGetSymbolAddress((void**)&rowptr, g_rowptr);
    cudaGetSymbolAddress((void**)&cursor, g_cursor);
    cudaGetSymbolAddress((void**)&adj, g_adj);

    float inv_n = 1.0f / (float)N;

    // ---- CSR build (once) ----
    cudaMemsetAsync(deg, 0, (size_t)N * sizeof(int));
    k_count<<<(E + 255) / 256, 256>>>(dst, deg, E);
    k_scan<<<1, 1024>>>(deg, rowptr, cursor, dinv, N);
    k_fill<<<(E + 255) / 256, 256>>>(src, dst, cursor, adj, E);

    int gemm_blocks = (N + 63) / 64;
    int agg_grid = 1536;

    // ---- layer 0: conv (zero buf0) -> agg (stats into buf0) ----
    gemm128_tc<false><<<gemm_blocks, 256>>>(x, W0, h1h, dinv,
        nullptr, nullptr, nullptr, nullptr, sum0, sq0, inv_n, N);
    k_agg128<true><<<agg_grid, 256>>>(h1h, rowptr, adj, dinv, b0, h2, sum0, sq0, N);

    // ---- layer 1: conv (bn from buf0, zero buf1) -> agg (stats into buf1) ----
    gemm128_tc<true><<<gemm_blocks, 256>>>(h2, W1, h1h, dinv,
        g0, bt0, sum0, sq0, sum1, sq1, inv_n, N);
    k_agg128<true><<<agg_grid, 256>>>(h1h, rowptr, adj, dinv, b1, h2, sum1, sq1, N);

    // ---- layer 2: conv (bn from buf1) -> agg + fused log_softmax ----
    gemm40<<<gemm_blocks, 256>>>(h2, W2, h1h, dinv, g1, bt1, sum1, sq1, inv_n, N);
    k_agg40<<<(N + 7) / 8, 256>>>(h1h, rowptr, adj, dinv, b2, out, N);
}

// round 17
// speedup vs baseline: 1.0977x; 1.0977x over previous
#include <cuda_runtime.h>
#include <cuda_fp16.h>
#include <math.h>
#include <stdint.h>

#define DH 128
#define NMAX 50016
#define EMAX 800000

// ---------------- scratch (device globals; no allocation allowed) ----------------
__device__ float  g_dinv[NMAX];
__device__ int    g_deg[NMAX];
__device__ int    g_rowptr[NMAX + 1];
__device__ int    g_cursor[NMAX];
__device__ int    g_adj[EMAX];
__device__ __half g_h1h[(size_t)NMAX * DH];  // fp16 dinv-scaled transformed features (gather operand)
__device__ float  g_h2[(size_t)NMAX * DH];   // aggregated features (fp32)
__device__ float  g_sum0[DH];
__device__ float  g_sq0[DH];
__device__ float  g_sum1[DH];
__device__ float  g_sq1[DH];

// ---------------- helpers ----------------
__device__ __forceinline__ uint32_t f2tf32(float x) {
    uint32_t u;
    asm("cvt.rna.tf32.f32 %0, %1;" : "=r"(u) : "f"(x));
    return u;
}

__device__ __forceinline__ void mma_tf32(float* c, const uint32_t* a, uint32_t b0, uint32_t b1) {
    asm volatile(
        "mma.sync.aligned.m16n8k8.row.col.f32.tf32.tf32.f32 "
        "{%0,%1,%2,%3}, {%4,%5,%6,%7}, {%8,%9}, {%0,%1,%2,%3};"
        : "+f"(c[0]), "+f"(c[1]), "+f"(c[2]), "+f"(c[3])
        : "r"(a[0]), "r"(a[1]), "r"(a[2]), "r"(a[3]), "r"(b0), "r"(b1));
}

__device__ __forceinline__ void acc_row128(float* a, const uint4& v) {
    float2 f0 = __half22float2(*reinterpret_cast<const __half2*>(&v.x));
    float2 f1 = __half22float2(*reinterpret_cast<const __half2*>(&v.y));
    float2 f2 = __half22float2(*reinterpret_cast<const __half2*>(&v.z));
    float2 f3 = __half22float2(*reinterpret_cast<const __half2*>(&v.w));
    a[0] += f0.x; a[1] += f0.y; a[2] += f1.x; a[3] += f1.y;
    a[4] += f2.x; a[5] += f2.y; a[6] += f3.x; a[7] += f3.y;
}

// ---------------- CSR build ----------------
__global__ void k_count(const int* __restrict__ dst, int* deg, int E) {
    int e = blockIdx.x * blockDim.x + threadIdx.x;
    if (e < E) atomicAdd(&deg[dst[e]], 1);
}

__global__ __launch_bounds__(1024) void k_scan(const int* __restrict__ deg,
                                               int* rowptr, int* cursor,
                                               float* dinv, int n)
{
    __shared__ int sm[1024];
    const int T = 1024;
    int tid = threadIdx.x;
    int chunk = (n + T - 1) / T;
    int beg = tid * chunk;
    int end = min(beg + chunk, n);
    if (beg > n) beg = n;
    if (end < beg) end = beg;

    int s = 0;
    for (int i = beg; i < end; i++) s += deg[i];
    sm[tid] = s;
    __syncthreads();
    for (int off = 1; off < T; off <<= 1) {
        int v = (tid >= off) ? sm[tid - off] : 0;
        __syncthreads();
        sm[tid] += v;
        __syncthreads();
    }
    int run = sm[tid] - s;
    for (int i = beg; i < end; i++) {
        int d = deg[i];
        rowptr[i] = run;
        cursor[i] = run;
        dinv[i] = rsqrtf((float)d + 1.0f);
        run += d;
    }
    if (tid == T - 1) rowptr[n] = sm[T - 1];
}

__global__ void k_fill(const int* __restrict__ src, const int* __restrict__ dst,
                       int* cursor, int* adj, int E)
{
    int e = blockIdx.x * blockDim.x + threadIdx.x;
    if (e < E) {
        int d = dst[e];
        int p = atomicAdd(&cursor[d], 1);
        adj[p] = src[e];
    }
}

// ---------------- tf32 tensor-core GEMM: Ch[n,128] = fp16( dinv * (op(A) @ W) ) ----------------
// BM=64 tile, 8 warps (4x2), warp = 16x64 via 8 m16n8k8 MMAs.
// BN: per-block bn affine from (ssum,ssq,gamma,beta) applied to A on load.
// Block 0 zeroes (zsum,zsq) for the aggregation kernel that follows.
template <bool BN>
__global__ __launch_bounds__(256) void gemm128_tc(
    const float* __restrict__ A, const float* __restrict__ W,
    __half* __restrict__ Ch, const float* __restrict__ dinv,
    const float* __restrict__ gamma, const float* __restrict__ beta,
    const float* __restrict__ ssum, const float* __restrict__ ssq,
    float* zsum, float* zsq, float inv_n, int nrows)
{
    __shared__ uint32_t sA[64][36];
    __shared__ uint32_t sW[32][136];
    __shared__ float sbna[DH];
    __shared__ float sbnb[DH];

    int tid = threadIdx.x;
    if (BN) {
        if (tid < DH) {
            float mu = ssum[tid] * inv_n;
            float var = ssq[tid] * inv_n - mu * mu;
            float rstd = rsqrtf(var + 1e-5f);
            float aa = gamma[tid] * rstd;
            sbna[tid] = aa;
            sbnb[tid] = beta[tid] - mu * aa;
        }
        __syncthreads();
    }
    if (blockIdx.x == 0 && tid < DH) {
        zsum[tid] = 0.f;
        zsq[tid] = 0.f;
    }

    int lane = tid & 31, warp = tid >> 5;
    int gq = lane >> 2, tq = lane & 3;
    int warpM = warp >> 1, warpN = warp & 1;
    int row0 = blockIdx.x * 64;

    float acc[8][4];
#pragma unroll
    for (int nt = 0; nt < 8; nt++)
#pragma unroll
        for (int i = 0; i < 4; i++) acc[nt][i] = 0.f;

    for (int slab = 0; slab < 4; slab++) {
        int kt = slab * 32;
#pragma unroll
        for (int i = 0; i < 2; i++) {
            int f = tid + i * 256;
            int r = f >> 3;
            int c4 = (f & 7) * 4;
            int gr = row0 + r;
            float4 v = (gr < nrows) ? *(const float4*)(A + (size_t)gr * 128 + kt + c4)
                                    : make_float4(0.f, 0.f, 0.f, 0.f);
            if (BN) {
                int c = kt + c4;
                v.x = fmaxf(v.x * sbna[c + 0] + sbnb[c + 0], 0.f);
                v.y = fmaxf(v.y * sbna[c + 1] + sbnb[c + 1], 0.f);
                v.z = fmaxf(v.z * sbna[c + 2] + sbnb[c + 2], 0.f);
                v.w = fmaxf(v.w * sbna[c + 3] + sbnb[c + 3], 0.f);
            }
            uint4 u = make_uint4(f2tf32(v.x), f2tf32(v.y), f2tf32(v.z), f2tf32(v.w));
            *(uint4*)&sA[r][c4] = u;
        }
#pragma unroll
        for (int i = 0; i < 4; i++) {
            int f = tid + i * 256;
            int kr = f >> 5;
            int c4 = (f & 31) * 4;
            float4 v = *(const float4*)(W + (size_t)(kt + kr) * 128 + c4);
            uint4 u = make_uint4(f2tf32(v.x), f2tf32(v.y), f2tf32(v.z), f2tf32(v.w));
            *(uint4*)&sW[kr][c4] = u;
        }
        __syncthreads();

#pragma unroll
        for (int k8 = 0; k8 < 4; k8++) {
            int kk = k8 * 8;
            uint32_t a[4];
            {
                int r = warpM * 16 + gq;
                a[0] = sA[r][kk + tq];
                a[1] = sA[r + 8][kk + tq];
                a[2] = sA[r][kk + tq + 4];
                a[3] = sA[r + 8][kk + tq + 4];
            }
#pragma unroll
            for (int nt = 0; nt < 8; nt++) {
                int n = warpN * 64 + nt * 8 + gq;
                uint32_t b0 = sW[kk + tq][n];
                uint32_t b1 = sW[kk + tq + 4][n];
                mma_tf32(acc[nt], a, b0, b1);
            }
        }
        __syncthreads();
    }

    {
        int r0 = row0 + warpM * 16 + gq;
        int r1 = r0 + 8;
        float d0 = (r0 < nrows) ? dinv[r0] : 0.f;
        float d1 = (r1 < nrows) ? dinv[r1] : 0.f;
#pragma unroll
        for (int nt = 0; nt < 8; nt++) {
            int col = warpN * 64 + nt * 8 + 2 * tq;
            if (r0 < nrows) {
                __half2 h = __floats2half2_rn(acc[nt][0] * d0, acc[nt][1] * d0);
                *(__half2*)(Ch + (size_t)r0 * 128 + col) = h;
            }
            if (r1 < nrows) {
                __half2 h = __floats2half2_rn(acc[nt][2] * d1, acc[nt][3] * d1);
                *(__half2*)(Ch + (size_t)r1 * 128 + col) = h;
            }
        }
    }
}

// ---------------- SGEMM: Ch[n,40] = fp16( dinv * (bn_relu(A)[n,128] @ W[128,40]) ) ----------------
__global__ __launch_bounds__(256) void gemm40(
    const float* __restrict__ A, const float* __restrict__ W,
    __half* __restrict__ Ch, const float* __restrict__ dinv,
    const float* __restrict__ gamma, const float* __restrict__ beta,
    const float* __restrict__ ssum, const float* __restrict__ ssq,
    float inv_n, int nrows)
{
    __shared__ float sA[16][64];
    __shared__ float sW[16][40];
    __shared__ float sbna[DH];
    __shared__ float sbnb[DH];
    int tid = threadIdx.x;
    if (tid < DH) {
        float mu = ssum[tid] * inv_n;
        float var = ssq[tid] * inv_n - mu * mu;
        float rstd = rsqrtf(var + 1e-5f);
        float aa = gamma[tid] * rstd;
        sbna[tid] = aa;
        sbnb[tid] = beta[tid] - mu * aa;
    }
    __syncthreads();

    int tx = tid & 15, ty = tid >> 4;
    int row0 = blockIdx.x * 64;

    float acc[4][3];
#pragma unroll
    for (int i = 0; i < 4; i++)
#pragma unroll
        for (int j = 0; j < 3; j++) acc[i][j] = 0.f;

    for (int kt = 0; kt < 128; kt += 16) {
        {
            int r = tid >> 2;
            int k4 = (tid & 3) * 4;
            int gr = row0 + r;
            float4 v = (gr < nrows) ? *(const float4*)(A + (size_t)gr * 128 + kt + k4)
                                    : make_float4(0.f, 0.f, 0.f, 0.f);
            int c = kt + k4;
            v.x = fmaxf(v.x * sbna[c + 0] + sbnb[c + 0], 0.f);
            v.y = fmaxf(v.y * sbna[c + 1] + sbnb[c + 1], 0.f);
            v.z = fmaxf(v.z * sbna[c + 2] + sbnb[c + 2], 0.f);
            v.w = fmaxf(v.w * sbna[c + 3] + sbnb[c + 3], 0.f);
            sA[k4 + 0][r] = v.x; sA[k4 + 1][r] = v.y;
            sA[k4 + 2][r] = v.z; sA[k4 + 3][r] = v.w;
        }
        for (int t = tid; t < 16 * 40; t += 256) {
            int kr = t / 40, c = t % 40;
            sW[kr][c] = W[(size_t)(kt + kr) * 40 + c];
        }
        __syncthreads();

#pragma unroll
        for (int k = 0; k < 16; k++) {
            float4 av = *(float4*)&sA[k][ty * 4];
            float a[4] = {av.x, av.y, av.z, av.w};
            float w0 = sW[k][tx];
            float w1 = sW[k][tx + 16];
            float w2 = (tx < 8) ? sW[k][tx + 32] : 0.f;
#pragma unroll
            for (int i = 0; i < 4; i++) {
                acc[i][0] += a[i] * w0;
                acc[i][1] += a[i] * w1;
                acc[i][2] += a[i] * w2;
            }
        }
        __syncthreads();
    }

#pragma unroll
    for (int i = 0; i < 4; i++) {
        int gr = row0 + ty * 4 + i;
        if (gr >= nrows) continue;
        float di = dinv[gr];
        Ch[(size_t)gr * 40 + tx]      = __float2half_rn(acc[i][0] * di);
        Ch[(size_t)gr * 40 + tx + 16] = __float2half_rn(acc[i][1] * di);
        if (tx < 8) Ch[(size_t)gr * 40 + tx + 32] = __float2half_rn(acc[i][2] * di);
    }
}

// ---------------- CSR gather aggregation, D=128 (R12 proven body) ----------------
// PAIRED fp16 gathers: row = 256B = 16 lanes x 16B; each LDG.128 serves TWO
// neighbor rows (lanes 0-15 even neighbor, 16-31 odd); shfl_xor(16) merge.
template <bool STATS>
__global__ __launch_bounds__(256) void k_agg128(
    const __half* __restrict__ hs, const int* __restrict__ rowptr,
    const int* __restrict__ adj, const float* __restrict__ dinv,
    const float* __restrict__ bias, float* __restrict__ out,
    float* osum, float* osq, int n)
{
    int tid = threadIdx.x;
    int warp = tid >> 5, lane = tid & 31;
    int side = lane >> 4;
    int fl = lane & 15;
    int g = fl * 8;

    float b[8];
    *(float4*)&b[0] = __ldg((const float4*)(bias + g));
    *(float4*)&b[4] = __ldg((const float4*)(bias + g + 4));

    float s[8], q[8];
#pragma unroll
    for (int i = 0; i < 8; i++) { s[i] = 0.f; q[i] = 0.f; }

    for (int node = blockIdx.x * 8 + warp; node < n; node += gridDim.x * 8) {
        int beg = __ldg(rowptr + node);
        int end = __ldg(rowptr + node + 1);

        float a[8];
#pragma unroll
        for (int i = 0; i < 8; i++) a[i] = 0.f;
        if (side == 0) {
            uint4 v = __ldg((const uint4*)(hs + (size_t)node * DH + g));
            acc_row128(a, v);
        }

        int j = beg;
        for (; j + 8 <= end; j += 8) {
            int ix[4];
#pragma unroll
            for (int u = 0; u < 4; u++) ix[u] = __ldg(adj + j + 2 * u + side);
            uint4 v[4];
#pragma unroll
            for (int u = 0; u < 4; u++)
                v[u] = __ldg((const uint4*)(hs + (size_t)ix[u] * DH + g));
#pragma unroll
            for (int u = 0; u < 4; u++) acc_row128(a, v[u]);
        }
        for (; j + 2 <= end; j += 2) {
            int ix = __ldg(adj + j + side);
            uint4 v = __ldg((const uint4*)(hs + (size_t)ix * DH + g));
            acc_row128(a, v);
        }
        if (j < end && side == 0) {
            int ix = __ldg(adj + j);
            uint4 v = __ldg((const uint4*)(hs + (size_t)ix * DH + g));
            acc_row128(a, v);
        }

#pragma unroll
        for (int i = 0; i < 8; i++)
            a[i] += __shfl_xor_sync(0xffffffffu, a[i], 16);

        if (side == 0) {
            float di = dinv[node];
            float o[8];
#pragma unroll
            for (int i = 0; i < 8; i++) o[i] = b[i] + a[i] * di;
            *(float4*)(out + (size_t)node * DH + g) =
                make_float4(o[0], o[1], o[2], o[3]);
            *(float4*)(out + (size_t)node * DH + g + 4) =
                make_float4(o[4], o[5], o[6], o[7]);
            if (STATS) {
#pragma unroll
                for (int i = 0; i < 8; i++) { s[i] += o[i]; q[i] += o[i] * o[i]; }
            }
        }
    }

    if (STATS) {
        __shared__ float rsum[8][DH];
        __shared__ float rsq[8][DH];
        if (side == 0) {
#pragma unroll
            for (int i = 0; i < 8; i++) {
                rsum[warp][g + i] = s[i];
                rsq[warp][g + i] = q[i];
            }
        }
        __syncthreads();
        if (tid < DH) {
            float aa = 0.f, bb = 0.f;
#pragma unroll
            for (int w = 0; w < 8; w++) { aa += rsum[w][tid]; bb += rsq[w][tid]; }
            atomicAdd(&osum[tid], aa);
            atomicAdd(&osq[tid], bb);
        }
    }
}

// ---------------- CSR gather aggregation D=40 (fp16 gather) + fused log_softmax (R12 body) ----------------
__global__ __launch_bounds__(256) void k_agg40(
    const __half* __restrict__ hs, const int* __restrict__ rowptr,
    const int* __restrict__ adj, const float* __restrict__ dinv,
    const float* __restrict__ bias, float* __restrict__ out, int n)
{
    int tid = threadIdx.x;
    int warp = tid >> 5, lane = tid & 31;
    int node = blockIdx.x * 8 + warp;
    if (node >= n) return;

    float4 o = make_float4(0.f, 0.f, 0.f, 0.f);
    if (lane < 10) {
        int g = lane * 4;
        int beg = __ldg(rowptr + node);
        int end = __ldg(rowptr + node + 1);
        float4 acc;
        {
            uint2 rw = __ldg((const uint2*)(hs + (size_t)node * 40 + g));
            float2 f0 = __half22float2(*reinterpret_cast<__half2*>(&rw.x));
            float2 f1 = __half22float2(*reinterpret_cast<__half2*>(&rw.y));
            acc = make_float4(f0.x, f0.y, f1.x, f1.y);
        }
        int j = beg;
        for (; j + 8 <= end; j += 8) {
            int sx[8];
#pragma unroll
            for (int u = 0; u < 8; u++) sx[u] = __ldg(adj + j + u);
            uint2 rw[8];
#pragma unroll
            for (int u = 0; u < 8; u++)
                rw[u] = __ldg((const uint2*)(hs + (size_t)sx[u] * 40 + g));
#pragma unroll
            for (int u = 0; u < 8; u++) {
                float2 f0 = __half22float2(*reinterpret_cast<__half2*>(&rw[u].x));
                float2 f1 = __half22float2(*reinterpret_cast<__half2*>(&rw[u].y));
                acc.x += f0.x; acc.y += f0.y; acc.z += f1.x; acc.w += f1.y;
            }
        }
        for (; j < end; j++) {
            int s = __ldg(adj + j);
            uint2 rw = __ldg((const uint2*)(hs + (size_t)s * 40 + g));
            float2 f0 = __half22float2(*reinterpret_cast<__half2*>(&rw.x));
            float2 f1 = __half22float2(*reinterpret_cast<__half2*>(&rw.y));
            acc.x += f0.x; acc.y += f0.y; acc.z += f1.x; acc.w += f1.y;
        }
        float di = dinv[node];
        float4 bvv = __ldg((const float4*)(bias + g));
        o = make_float4(bvv.x + acc.x * di, bvv.y + acc.y * di,
                        bvv.z + acc.z * di, bvv.w + acc.w * di);
    }

    float m = (lane < 10) ? fmaxf(fmaxf(o.x, o.y), fmaxf(o.z, o.w)) : -INFINITY;
#pragma unroll
    for (int off = 16; off > 0; off >>= 1)
        m = fmaxf(m, __shfl_xor_sync(0xffffffffu, m, off));
    float s = (lane < 10) ? (expf(o.x - m) + expf(o.y - m) + expf(o.z - m) + expf(o.w - m)) : 0.f;
#pragma unroll
    for (int off = 16; off > 0; off >>= 1)
        s += __shfl_xor_sync(0xffffffffu, s, off);
    float l = m + logf(s);
    if (lane < 10) {
        *(float4*)(out + (size_t)node * 40 + lane * 4) =
            make_float4(o.x - l, o.y - l, o.z - l, o.w - l);
    }
}

// ---------------- host orchestration (single stream, graph-capture safe) ----------------
extern "C" void kernel_launch(void* const* d_in, const int* in_sizes, int n_in,
                              void* d_out, int out_size)
{
    const float* x   = (const float*)d_in[0];
    const int*   ei  = (const int*)d_in[1];
    const float* W0  = (const float*)d_in[2];
    const float* b0  = (const float*)d_in[3];
    const float* W1  = (const float*)d_in[4];
    const float* b1  = (const float*)d_in[5];
    const float* W2  = (const float*)d_in[6];
    const float* b2  = (const float*)d_in[7];
    const float* g0  = (const float*)d_in[8];
    const float* bt0 = (const float*)d_in[9];
    const float* g1  = (const float*)d_in[10];
    const float* bt1 = (const float*)d_in[11];
    float* out = (float*)d_out;

    int N = in_sizes[0] / DH;
    int E = in_sizes[1] / 2;
    const int* src = ei;
    const int* dst = ei + E;

    float *dinv, *h2, *sum0, *sq0, *sum1, *sq1;
    __half* h1h;
    int *deg, *rowptr, *cursor, *adj;
    cudaGetSymbolAddress((void**)&dinv, g_dinv);
    cudaGetSymbolAddress((void**)&h1h, g_h1h);
    cudaGetSymbolAddress((void**)&h2, g_h2);
    cudaGetSymbolAddress((void**)&sum0, g_sum0);
    cudaGetSymbolAddress((void**)&sq0, g_sq0);
    cudaGetSymbolAddress((void**)&sum1, g_sum1);
    cudaGetSymbolAddress((void**)&sq1, g_sq1);
    cudaGetSymbolAddress((void**)&deg, g_deg);
    cudaGetSymbolAddress((void**)&rowptr, g_rowptr);
    cudaGetSymbolAddress((void**)&cursor, g_cursor);
    cudaGetSymbolAddress((void**)&adj, g_adj);

    float inv_n = 1.0f / (float)N;
    int gemm_blocks = (N + 63) / 64;
    int agg_grid = 1536;

    // ---- CSR build (once) ----
    cudaMemsetAsync(deg, 0, (size_t)N * sizeof(int));
    k_count<<<(E + 255) / 256, 256>>>(dst, deg, E);
    k_scan<<<1, 1024>>>(deg, rowptr, cursor, dinv, N);
    k_fill<<<(E + 255) / 256, 256>>>(src, dst, cursor, adj, E);

    // ---- layer 0: conv (zero buf0) -> agg (stats into buf0) ----
    gemm128_tc<false><<<gemm_blocks, 256>>>(x, W0, h1h, dinv,
        nullptr, nullptr, nullptr, nullptr, sum0, sq0, inv_n, N);
    k_agg128<true><<<agg_grid, 256>>>(h1h, rowptr, adj, dinv, b0, h2, sum0, sq0, N);

    // ---- layer 1: conv (bn from buf0, zero buf1) -> agg (stats into buf1) ----
    gemm128_tc<true><<<gemm_blocks, 256>>>(h2, W1, h1h, dinv,
        g0, bt0, sum0, sq0, sum1, sq1, inv_n, N);
    k_agg128<true><<<agg_grid, 256>>>(h1h, rowptr, adj, dinv, b1, h2, sum1, sq1, N);

    // ---- layer 2: conv (bn from buf1) -> agg + fused log_softmax ----
    gemm40<<<gemm_blocks, 256>>>(h2, W2, h1h, dinv, g1, bt1, sum1, sq1, inv_n, N);
    k_agg40<<<(N + 7) / 8, 256>>>(h1h, rowptr, adj, dinv, b2, out, N);
}